// round 4
// baseline (speedup 1.0000x reference)
#include <cuda_runtime.h>
#include <cuda_bf16.h>

#define HW      589824      // 768*768
#define NG      147456      // HW/4 int4-groups per batch
#define BPB     192         // blocks per batch
#define TPB     160         // 5 warps: one per float2 pack
#define ITERS   24          // NG / BPB / 32
#define NB      8
#define NC      9
#define NOUT    90          // 5 packs * 9 classes * 2

__device__ float g_part[NB * BPB * NOUT];
__device__ float g_tot[NB * NOUT];
__device__ int   g_bcnt[NB];
__device__ int   g_fcnt;

__global__ void __launch_bounds__(TPB, 10) fused_kernel(
    const int* __restrict__ masks, const float* __restrict__ outs,
    float* __restrict__ out)
{
    // per-lane-private accumulators: [warp(pack)][class][lane], lane innermost
    __shared__ float2 sh[5 * NC * 32];     // 11520 B
    __shared__ int s_last;
    __shared__ float per[64], pres[64];

    const int tid  = threadIdx.x;
    const int lane = tid & 31;
    const int w    = tid >> 5;             // pack id 0..4
    const int b    = blockIdx.y;
    const int blk  = blockIdx.x;

    float2* acc = sh + w * NC * 32 + lane; // this lane's 9 slots, stride 32

    #pragma unroll
    for (int m = 0; m < NC; m++) acc[m * 32] = make_float2(0.f, 0.f);
    // no __syncthreads needed: slots are strictly lane-private

    const int4*   m4 = (const int4*)(masks + (size_t)b * HW);
    const float4* o4 = (const float4*)(outs + (size_t)b * NC * HW);
    const bool has_c1 = (w < 4);
    const float4* p0 = o4 + (size_t)(2 * w) * NG;
    const float4* p1 = o4 + (size_t)(has_c1 ? 2 * w + 1 : 8) * NG;

    const int gbase = blk * (32 * ITERS);

    #pragma unroll 2
    for (int it = 0; it < ITERS; it++) {
        int g = gbase + it * 32 + lane;
        int4 mm = m4[g];
        float4 va = p0[g];
        float4 vb = has_c1 ? p1[g] : make_float4(1.f, 1.f, 1.f, 1.f);

        #pragma unroll
        for (int j = 0; j < 4; j++) {
            int m = (j == 0) ? mm.x : (j == 1) ? mm.y : (j == 2) ? mm.z : mm.w;
            m = min(max(m, 0), NC - 1);
            float ax = (j == 0) ? va.x : (j == 1) ? va.y : (j == 2) ? va.z : va.w;
            float bx = (j == 0) ? vb.x : (j == 1) ? vb.y : (j == 2) ? vb.z : vb.w;
            float2 t = acc[m * 32];
            t.x += ax;
            t.y += bx;
            acc[m * 32] = t;
        }
    }

    // warp-level reduction: 18 values via shfl butterfly
    float vals[18];
    #pragma unroll
    for (int m = 0; m < NC; m++) {
        float2 t = acc[m * 32];
        vals[2 * m]     = t.x;
        vals[2 * m + 1] = t.y;
    }
    #pragma unroll
    for (int off = 16; off > 0; off >>= 1) {
        #pragma unroll
        for (int i = 0; i < 18; i++)
            vals[i] += __shfl_xor_sync(0xFFFFFFFFu, vals[i], off);
    }
    if (lane == 0) {
        #pragma unroll
        for (int i = 0; i < 18; i++)
            g_part[((size_t)(b * BPB + blk)) * NOUT + w * 18 + i] = vals[i];
    }
    __threadfence();
    __syncthreads();
    if (tid == 0) s_last = (atomicAdd(&g_bcnt[b], 1) == BPB - 1);
    __syncthreads();
    if (!s_last) return;

    // ── per-batch reducer (8 in parallel, one per batch) ──
    __threadfence();
    if (tid < NOUT) {
        float s = 0.0f;
        #pragma unroll 8
        for (int k = 0; k < BPB; k++)
            s += g_part[((size_t)(b * BPB + k)) * NOUT + tid];
        g_tot[b * NOUT + tid] = s;
    }
    __threadfence();
    __syncthreads();
    if (tid == 0) s_last = (atomicAdd(&g_fcnt, 1) == NB - 1);
    __syncthreads();
    if (!s_last) return;

    // ── global final block: log-softmax loss over 64 protos ──
    __threadfence();
    if (tid < 64) {
        int bb = tid / 8, k = tid % 8 + 1;          // classes 1..8
        float cnt   = g_tot[bb * NOUT + 4 * 18 + k * 2 + 1];
        float denom = fmaxf(cnt, 1.0f);
        float p[NC], mx = -1e30f;
        #pragma unroll
        for (int c = 0; c < NC; c++) {
            p[c] = g_tot[bb * NOUT + (c >> 1) * 18 + k * 2 + (c & 1)] / denom;
            mx = fmaxf(mx, p[c]);
        }
        float se = 0.0f;
        #pragma unroll
        for (int c = 0; c < NC; c++) se += expf(p[c] - mx);
        float lse = mx + logf(se);
        float l = 0.0f;
        #pragma unroll
        for (int c = 0; c < NC; c++) {
            float tgt = (c == k) ? 0.9f : 0.0125f;
            l += tgt * (p[c] - lse);
        }
        bool present = cnt > 0.0f;
        per[tid]  = present ? -l   : 0.0f;
        pres[tid] = present ? 1.0f : 0.0f;
    }
    __syncthreads();
    if (tid == 0) {
        float L = 0.0f, P = 0.0f;
        #pragma unroll
        for (int i = 0; i < 64; i++) { L += per[i]; P += pres[i]; }
        out[0] = L / fmaxf(P, 1.0f);
        g_fcnt = 0;
    }
    if (tid < NB) g_bcnt[tid] = 0;
}

extern "C" void kernel_launch(void* const* d_in, const int* in_sizes, int n_in,
                              void* d_out, int out_size)
{
    const int* masks;
    const float* outs;
    if (in_sizes[0] == NB * HW) {
        masks = (const int*)d_in[0];
        outs  = (const float*)d_in[1];
    } else {
        masks = (const int*)d_in[1];
        outs  = (const float*)d_in[0];
    }
    float* out = (float*)d_out;

    dim3 grid(BPB, NB);
    fused_kernel<<<grid, TPB>>>(masks, outs, out);
}